// round 12
// baseline (speedup 1.0000x reference)
#include <cuda_runtime.h>
#include <cuda_fp16.h>
#include <cstdint>
#include <cstddef>

#define NB 8
#define NC 512
#define NIC 64
#define NHW 9216

// ---------------- scratch (device globals; no runtime allocation) ----------
__device__ float g_q [NB*NIC*NHW];
__device__ float g_k [NB*NIC*NHW];
__device__ float g_qt[NB*NIC*NHW];
__device__ float g_kt[NB*NIC*NHW];
__device__ float g_Ew[(size_t)NB*NHW*96];      // [b][h][w][v] row logits (fp32)
__device__ float g_Eh[(size_t)NB*NHW*96];      // [b][w][h][g] col logits (fp32)
__device__ __half g_Awh[(size_t)NB*NHW*96];    // softmax row part
__device__ __half g_Ahh[(size_t)NB*NHW*96];    // softmax col part (transposed layout)
__device__ __half g_v2 [(size_t)NB*NHW*NC];    // v = Wv@x, channel-minor [b][h][w][c]
__device__ __half g_o2w[(size_t)NB*NHW*NC];    // row-agg out [b][h][w][c]
__device__ __half g_o2h[(size_t)NB*NHW*NC];    // col-agg out [b][w][h][c]

// ---------------- helpers ---------------------------------------------------
__device__ __forceinline__ void mma16h(float* d, const unsigned* a, const unsigned* b){
  asm volatile("mma.sync.aligned.m16n8k16.row.col.f32.f16.f16.f32 "
    "{%0,%1,%2,%3},{%4,%5,%6,%7},{%8,%9},{%0,%1,%2,%3};\n"
    :"+f"(d[0]),"+f"(d[1]),"+f"(d[2]),"+f"(d[3])
    :"r"(a[0]),"r"(a[1]),"r"(a[2]),"r"(a[3]),"r"(b[0]),"r"(b[1]));
}
__device__ __forceinline__ unsigned packh2(float a, float b){
  __half2 v=__floats2half2_rn(a,b); return *reinterpret_cast<unsigned*>(&v);
}
__device__ __forceinline__ void split2(float v0, float v1, unsigned& hi, unsigned& lo){
  __half h0=__float2half_rn(v0), h1=__float2half_rn(v1);
  float  r0=v0-__half2float(h0), r1=v1-__half2float(h1);
  __half2 hv=__halves2half2(h0,h1);
  __half2 lv=__floats2half2_rn(r0,r1);
  hi=*reinterpret_cast<unsigned*>(&hv);
  lo=*reinterpret_cast<unsigned*>(&lv);
}

// ---------------- q/k projection: [Wq;Wk](128x512) @ x_b, split-fp16 -------
__global__ __launch_bounds__(256,2) void gemm_qk(
  const float* __restrict__ x,
  const float* __restrict__ Wq, const float* __restrict__ bq,
  const float* __restrict__ Wk, const float* __restrict__ bk)
{
  __shared__ unsigned Ahs[16][136], Als[16][136], Bhs[16][136], Bls[16][136];
  const int bI=blockIdx.y, n0=blockIdx.x*128;
  const float* Bp = x + (size_t)bI*NC*NHW;
  const int t=threadIdx.x, lane=t&31, grp=lane>>2, tig=lane&3;
  const int warp=t>>5, wm=warp>>2, wn=warp&3;

  float acc[4][4][4];
#pragma unroll
  for(int i=0;i<4;i++)for(int j=0;j<4;j++)for(int r=0;r<4;r++) acc[i][j][r]=0.f;

  const int am=t&127, aks=(t>>7)*16;
  const float* Ar = (am<64)? Wq+(size_t)am*NC : Wk+(size_t)(am-64)*NC;
  const int bn=t&127, bkp=(t>>7)*8;

  float fb0[8], fb1[8];
#pragma unroll
  for(int j=0;j<8;j++){
    int row=2*(bkp+j);
    fb0[j]=Bp[(size_t)row*NHW+n0+bn];
    fb1[j]=Bp[(size_t)(row+1)*NHW+n0+bn];
  }

  for(int k0=0;k0<NC;k0+=32){
    float av[16];
#pragma unroll
    for(int i=0;i<4;i++) *(float4*)(av+4*i)=*(const float4*)(Ar+k0+aks+4*i);
    if(k0) __syncthreads();
#pragma unroll
    for(int j=0;j<8;j++){
      unsigned hi,lo; split2(av[2*j],av[2*j+1],hi,lo);
      Ahs[aks/2+j][am]=hi; Als[aks/2+j][am]=lo;
    }
#pragma unroll
    for(int j=0;j<8;j++){
      unsigned hi,lo; split2(fb0[j],fb1[j],hi,lo);
      Bhs[bkp+j][bn]=hi; Bls[bkp+j][bn]=lo;
    }
    __syncthreads();
    if(k0+32<NC){
#pragma unroll
      for(int j=0;j<8;j++){
        int row=k0+32+2*(bkp+j);
        fb0[j]=Bp[(size_t)row*NHW+n0+bn];
        fb1[j]=Bp[(size_t)(row+1)*NHW+n0+bn];
      }
    }
#pragma unroll
    for(int s=0;s<2;s++){
      const int pb=s*8;
      unsigned ah[4][4], al[4][4], bh[4][2], bl[4][2];
#pragma unroll
      for(int mt=0;mt<4;mt++){
        int mbx=wm*64+mt*16;
        ah[mt][0]=Ahs[pb+tig][mbx+grp];   ah[mt][1]=Ahs[pb+tig][mbx+grp+8];
        ah[mt][2]=Ahs[pb+tig+4][mbx+grp]; ah[mt][3]=Ahs[pb+tig+4][mbx+grp+8];
        al[mt][0]=Als[pb+tig][mbx+grp];   al[mt][1]=Als[pb+tig][mbx+grp+8];
        al[mt][2]=Als[pb+tig+4][mbx+grp]; al[mt][3]=Als[pb+tig+4][mbx+grp+8];
      }
#pragma unroll
      for(int nt=0;nt<4;nt++){
        int nb=wn*32+nt*8;
        bh[nt][0]=Bhs[pb+tig][nb+grp]; bh[nt][1]=Bhs[pb+tig+4][nb+grp];
        bl[nt][0]=Bls[pb+tig][nb+grp]; bl[nt][1]=Bls[pb+tig+4][nb+grp];
      }
#pragma unroll
      for(int mt=0;mt<4;mt++)
#pragma unroll
        for(int nt=0;nt<4;nt++){
          mma16h(acc[mt][nt], ah[mt], bh[nt]);
          mma16h(acc[mt][nt], al[mt], bh[nt]);
          mma16h(acc[mt][nt], ah[mt], bl[nt]);
        }
    }
  }
#pragma unroll
  for(int mt=0;mt<4;mt++)
#pragma unroll
    for(int half=0;half<2;half++){
      int rr=wm*64+mt*16+grp+half*8;
      float bias; float* dst;
      if(rr<64){bias=bq[rr]; dst=g_q+((size_t)bI*NIC+rr)*NHW;}
      else     {bias=bk[rr-64]; dst=g_k+((size_t)bI*NIC+(rr-64))*NHW;}
#pragma unroll
      for(int nt=0;nt<4;nt++){
        int cc=n0+wn*32+nt*8+tig*2;
        float2 v; v.x=acc[mt][nt][half*2]+bias; v.y=acc[mt][nt][half*2+1]+bias;
        *(float2*)(dst+cc)=v;
      }
    }
}

// ---------------- v projection: Wv(512x512) @ x_b -> v2 channel-minor ------
__global__ __launch_bounds__(256,2) void gemm_v(
  const float* __restrict__ x, const float* __restrict__ Wv)
{
  __shared__ __align__(16) unsigned sbuf[4*16*136];
  unsigned (*Ahs)[136] = (unsigned(*)[136])(sbuf);
  unsigned (*Bhs)[136] = (unsigned(*)[136])(sbuf+2176);

  const int bI=blockIdx.z, n0=blockIdx.x*128, m0v=blockIdx.y*128;
  const float* Bp = x + (size_t)bI*NC*NHW;
  const int t=threadIdx.x, lane=t&31, grp=lane>>2, tig=lane&3;
  const int warp=t>>5, wm=warp>>2, wn=warp&3;

  float acc[4][4][4];
#pragma unroll
  for(int i=0;i<4;i++)for(int j=0;j<4;j++)for(int r=0;r<4;r++) acc[i][j][r]=0.f;

  const int am=t&127, aks=(t>>7)*16;
  const float* Ar = Wv + (size_t)(m0v+am)*NC;
  const int bn=t&127, bkp=(t>>7)*8;

  float fa[16], fb0[8], fb1[8];
#pragma unroll
  for(int i=0;i<4;i++) *(float4*)(fa+4*i)=*(const float4*)(Ar+aks+4*i);
#pragma unroll
  for(int j=0;j<8;j++){
    int row=2*(bkp+j);
    fb0[j]=Bp[(size_t)row*NHW+n0+bn];
    fb1[j]=Bp[(size_t)(row+1)*NHW+n0+bn];
  }

  for(int k0=0;k0<NC;k0+=32){
    if(k0) __syncthreads();
#pragma unroll
    for(int j=0;j<8;j++) Ahs[aks/2+j][am]=packh2(fa[2*j],fa[2*j+1]);
#pragma unroll
    for(int j=0;j<8;j++) Bhs[bkp+j][bn]=packh2(fb0[j],fb1[j]);
    __syncthreads();
    if(k0+32<NC){
#pragma unroll
      for(int i=0;i<4;i++) *(float4*)(fa+4*i)=*(const float4*)(Ar+k0+32+aks+4*i);
#pragma unroll
      for(int j=0;j<8;j++){
        int row=k0+32+2*(bkp+j);
        fb0[j]=Bp[(size_t)row*NHW+n0+bn];
        fb1[j]=Bp[(size_t)(row+1)*NHW+n0+bn];
      }
    }
#pragma unroll
    for(int s=0;s<2;s++){
      const int pb=s*8;
      unsigned a[4][4], b[4][2];
#pragma unroll
      for(int mt=0;mt<4;mt++){
        int mbx=wm*64+mt*16;
        a[mt][0]=Ahs[pb+tig][mbx+grp];   a[mt][1]=Ahs[pb+tig][mbx+grp+8];
        a[mt][2]=Ahs[pb+tig+4][mbx+grp]; a[mt][3]=Ahs[pb+tig+4][mbx+grp+8];
      }
#pragma unroll
      for(int nt=0;nt<4;nt++){
        int nb=wn*32+nt*8;
        b[nt][0]=Bhs[pb+tig][nb+grp]; b[nt][1]=Bhs[pb+tig+4][nb+grp];
      }
#pragma unroll
      for(int mt=0;mt<4;mt++)
#pragma unroll
        for(int nt=0;nt<4;nt++) mma16h(acc[mt][nt], a[mt], b[nt]);
    }
  }
  // epilogue: transpose 128m(c) x 128n(pix) tile through smem, write v2
  __syncthreads();
  __half (*st)[136] = (__half(*)[136])sbuf;
#pragma unroll
  for(int mt=0;mt<4;mt++)
#pragma unroll
    for(int half=0;half<2;half++){
      int m=wm*64+mt*16+grp+half*8;
#pragma unroll
      for(int nt=0;nt<4;nt++){
        int n=wn*32+nt*8+tig*2;
        st[n][m]  =__float2half(acc[mt][nt][half*2]);
        st[n+1][m]=__float2half(acc[mt][nt][half*2+1]);
      }
    }
  __syncthreads();
  __half2* v2p=(__half2*)(g_v2 + ((size_t)bI*NHW + n0)*NC + m0v);
#pragma unroll
  for(int i=0;i<32;i++){
    int lin=i*256+t, p=lin>>6, cj=lin&63;
    v2p[(size_t)p*(NC/2)+cj] = *(__half2*)&st[p][2*cj];
  }
}

// ---------------- fp32 96x96 transpose for q,k ------------------------------
__global__ __launch_bounds__(256) void transpose_qk(){
  __shared__ float s[96][97];
  const float* in  = blockIdx.y ? g_k  : g_q;
  float*       out = blockIdx.y ? g_kt : g_qt;
  size_t base=(size_t)blockIdx.x*NHW;
  int t=threadIdx.x;
#pragma unroll
  for(int i=0;i<36;i++){int idx=t+i*256; s[idx/96][idx%96]=in[base+idx];}
  __syncthreads();
#pragma unroll
  for(int i=0;i<36;i++){int idx=t+i*256; out[base+idx]=s[idx%96][idx/96];}
}

// ---------------- logits: split-fp16, fp32 E output -------------------------
__global__ __launch_bounds__(256) void logits_kernel(){
  __shared__ unsigned Qh[16][104], Ql[16][104], Kh[16][104], Kl[16][104];
  const int slab=blockIdx.x, mode=blockIdx.y;
  const int bI=slab/96, s=slab%96;
  const float* Qp=(mode? g_qt : g_q) + (size_t)bI*NIC*NHW + s*96;
  const float* Kp=(mode? g_kt : g_k) + (size_t)bI*NIC*NHW + s*96;
  float* Ep=(mode? g_Eh : g_Ew) + (size_t)slab*NHW;
  const int t=threadIdx.x, lane=t&31, grp=lane>>2, tig=lane&3;
  const int warp=t>>5, wm=warp>>2, wn=warp&3;

  float acc[3][3][4];
#pragma unroll
  for(int i=0;i<3;i++)for(int j=0;j<3;j++)for(int r=0;r<4;r++) acc[i][j][r]=0.f;

  for(int c0=0;c0<NIC;c0+=32){
    if(c0) __syncthreads();
#pragma unroll
    for(int i=0;i<6;i++){
      int idx=t+i*256, p=idx/96, w=idx%96;
      int ch=c0+2*p;
      float q0=Qp[(size_t)ch*NHW+w],  q1=Qp[(size_t)(ch+1)*NHW+w];
      float k0v=Kp[(size_t)ch*NHW+w], k1v=Kp[(size_t)(ch+1)*NHW+w];
      unsigned hi,lo;
      split2(q0,q1,hi,lo); Qh[p][w]=hi; Ql[p][w]=lo;
      split2(k0v,k1v,hi,lo); Kh[p][w]=hi; Kl[p][w]=lo;
    }
    __syncthreads();
#pragma unroll
    for(int s2=0;s2<2;s2++){
      const int pb=s2*8;
      unsigned ah[3][4], al[3][4], bh[3][2], bl[3][2];
#pragma unroll
      for(int mt=0;mt<3;mt++){
        int mbx=wm*48+mt*16;
        ah[mt][0]=Qh[pb+tig][mbx+grp];   ah[mt][1]=Qh[pb+tig][mbx+grp+8];
        ah[mt][2]=Qh[pb+tig+4][mbx+grp]; ah[mt][3]=Qh[pb+tig+4][mbx+grp+8];
        al[mt][0]=Ql[pb+tig][mbx+grp];   al[mt][1]=Ql[pb+tig][mbx+grp+8];
        al[mt][2]=Ql[pb+tig+4][mbx+grp]; al[mt][3]=Ql[pb+tig+4][mbx+grp+8];
      }
#pragma unroll
      for(int nt=0;nt<3;nt++){
        int nb=wn*24+nt*8;
        bh[nt][0]=Kh[pb+tig][nb+grp]; bh[nt][1]=Kh[pb+tig+4][nb+grp];
        bl[nt][0]=Kl[pb+tig][nb+grp]; bl[nt][1]=Kl[pb+tig+4][nb+grp];
      }
#pragma unroll
      for(int mt=0;mt<3;mt++)
#pragma unroll
        for(int nt=0;nt<3;nt++){
          mma16h(acc[mt][nt], ah[mt], bh[nt]);
          mma16h(acc[mt][nt], al[mt], bh[nt]);
          mma16h(acc[mt][nt], ah[mt], bl[nt]);
        }
    }
  }
#pragma unroll
  for(int mt=0;mt<3;mt++)
#pragma unroll
    for(int half=0;half<2;half++){
      int row=wm*48+mt*16+grp+half*8;
#pragma unroll
      for(int nt=0;nt<3;nt++){
        int col=wn*24+nt*8+tig*2;
        float2 v; v.x=acc[mt][nt][half*2]; v.y=acc[mt][nt][half*2+1];
        *(float2*)(Ep+(size_t)row*96+col)=v;
      }
    }
}

// ---------------- fused 192-wide softmax -> fp16 A --------------------------
__global__ __launch_bounds__(256) void softmax_kernel(){
  const int warp=threadIdx.x>>5, lane=threadIdx.x&31;
  const int p=blockIdx.x*8+warp;
  const int bI=p/NHW, rem=p%NHW, h=rem/96, w=rem%96;
  const float* ehp = g_Eh + ((size_t)(bI*96+w)*96 + h)*96;
  const float* ewp = g_Ew + (size_t)p*96;
  __half* ahp = g_Ahh + ((size_t)(bI*96+w)*96 + h)*96;
  __half* awp = g_Awh + (size_t)p*96;
  float eh[3], ew[3], m=-1e30f;
#pragma unroll
  for(int j=0;j<3;j++){
    int g=lane+32*j;
    eh[j]=(g==h)? -1e30f : ehp[g];
    ew[j]=ewp[g];
    m=fmaxf(m,fmaxf(eh[j],ew[j]));
  }
#pragma unroll
  for(int o=16;o>0;o>>=1) m=fmaxf(m,__shfl_xor_sync(0xffffffffu,m,o));
  float sum=0.f;
#pragma unroll
  for(int j=0;j<3;j++){
    eh[j]=__expf(eh[j]-m); ew[j]=__expf(ew[j]-m); sum+=eh[j]+ew[j];
  }
#pragma unroll
  for(int o=16;o>0;o>>=1) sum+=__shfl_xor_sync(0xffffffffu,sum,o);
  float inv=1.f/sum;
#pragma unroll
  for(int j=0;j<3;j++){
    int g=lane+32*j;
    ahp[g]=__float2half((g==h)?0.f:eh[j]*inv);
    awp[g]=__float2half(ew[j]*inv);
  }
}

// ---------------- aggregation: o2 = A_slab(96x96) @ v_slab(96x512) ---------
__global__ __launch_bounds__(256) void agg_v(){
  __shared__ unsigned As[24][104];
  __shared__ unsigned Bs[24][264];
  const int nck=blockIdx.x, slab=blockIdx.y, mode=blockIdx.z;
  const int bI=slab/96, s=slab%96, n0=nck*256;
  const __half* Ap=(mode? g_Ahh : g_Awh) + (size_t)slab*NHW;
  const __half* Bb = g_v2 + (mode ? ((size_t)bI*NHW + s)*NC : (size_t)slab*96*NC);
  const size_t rstride = mode ? (size_t)96*NC : (size_t)NC;
  __half* Op=(mode? g_o2h : g_o2w) + (size_t)slab*96*NC;
  const int t=threadIdx.x, lane=t&31, grp=lane>>2, tig=lane&3;
  const int warp=t>>5, wm=warp>>2, wn=warp&3;

  float acc[3][8][4];
#pragma unroll
  for(int i=0;i<3;i++)for(int j=0;j<8;j++)for(int r=0;r<4;r++) acc[i][j][r]=0.f;

  for(int kc=0;kc<96;kc+=48){
    if(kc) __syncthreads();
#pragma unroll
    for(int i=0;i<9;i++){
      int idx=t+i*256, m=idx/24, kp=idx%24;
      As[kp][m]=*(const unsigned*)(Ap + (size_t)m*96 + kc + 2*kp);
    }
#pragma unroll
    for(int i=0;i<12;i++){
      int idx=t+i*256, kp=idx/128, nj=idx%128;
      const __half* r0=Bb + (size_t)(kc+2*kp)*rstride + n0 + 2*nj;
      unsigned u0=*(const unsigned*)r0;
      unsigned u1=*(const unsigned*)(r0+rstride);
      Bs[kp][2*nj]  =(u0&0xffffu)|(u1<<16);
      Bs[kp][2*nj+1]=(u0>>16)|(u1&0xffff0000u);
    }
    __syncthreads();
#pragma unroll
    for(int s2=0;s2<3;s2++){
      const int pb=s2*8;
      unsigned a[3][4], b[8][2];
#pragma unroll
      for(int mt=0;mt<3;mt++){
        int mbx=wm*48+mt*16;
        a[mt][0]=As[pb+tig][mbx+grp];   a[mt][1]=As[pb+tig][mbx+grp+8];
        a[mt][2]=As[pb+tig+4][mbx+grp]; a[mt][3]=As[pb+tig+4][mbx+grp+8];
      }
#pragma unroll
      for(int nt=0;nt<8;nt++){
        int nb=wn*64+nt*8;
        b[nt][0]=Bs[pb+tig][nb+grp]; b[nt][1]=Bs[pb+tig+4][nb+grp];
      }
#pragma unroll
      for(int mt=0;mt<3;mt++)
#pragma unroll
        for(int nt=0;nt<8;nt++) mma16h(acc[mt][nt], a[mt], b[nt]);
    }
  }
#pragma unroll
  for(int mt=0;mt<3;mt++)
#pragma unroll
    for(int half=0;half<2;half++){
      int m=wm*48+mt*16+grp+half*8;
#pragma unroll
      for(int nt=0;nt<8;nt++){
        int col=n0+wn*64+nt*8+tig*2;
        *(__half2*)(Op + (size_t)m*NC + col) =
            __floats2half2_rn(acc[mt][nt][half*2], acc[mt][nt][half*2+1]);
      }
    }
}

// ---------------- combine: out = gamma*(o2w + o2h^T + bv) + x --------------
__global__ __launch_bounds__(256) void combine_kernel(
  const float* __restrict__ bv, const float* __restrict__ gamma,
  const float* __restrict__ x, float* __restrict__ out)
{
  __shared__ float s[96][65];
  const int c0=blockIdx.x*64, h=blockIdx.y, bI=blockIdx.z;
  const int t=threadIdx.x;
  const float gam=gamma[0];
#pragma unroll
  for(int i=0;i<12;i++){
    int idx=t+i*256, w=idx/32, cj=idx%32;
    __half2 aw=*(const __half2*)(g_o2w + ((size_t)(bI*96+h)*96+w)*NC + c0 + 2*cj);
    __half2 ah=*(const __half2*)(g_o2h + ((size_t)(bI*96+w)*96+h)*NC + c0 + 2*cj);
    float2 fa=__half22float2(aw), fb=__half22float2(ah);
    s[w][2*cj]=fa.x+fb.x; s[w][2*cj+1]=fa.y+fb.y;
  }
  __syncthreads();
#pragma unroll
  for(int i=0;i<24;i++){
    int idx=t+i*256, c=idx/96, w=idx%96;
    size_t a=((size_t)bI*NC + c0+c)*NHW + (size_t)h*96 + w;
    out[a]=gam*(s[w][c]+bv[c0+c])+x[a];
  }
}

// ---------------- launch: two-stream overlap of qk-chain and v-chain -------
extern "C" void kernel_launch(void* const* d_in, const int* in_sizes, int n_in,
                              void* d_out, int out_size){
  const float* x    =(const float*)d_in[0];
  const float* Wq   =(const float*)d_in[1];
  const float* bq   =(const float*)d_in[2];
  const float* Wk   =(const float*)d_in[3];
  const float* bk   =(const float*)d_in[4];
  const float* Wv   =(const float*)d_in[5];
  const float* bv   =(const float*)d_in[6];
  const float* gamma=(const float*)d_in[7];
  float* out=(float*)d_out;

  static cudaStream_t s1 = nullptr;
  static cudaEvent_t evRoot = nullptr, evV = nullptr;
  if(!s1){
    cudaStreamCreateWithFlags(&s1, cudaStreamNonBlocking);
    cudaEventCreateWithFlags(&evRoot, cudaEventDisableTiming);
    cudaEventCreateWithFlags(&evV,   cudaEventDisableTiming);
  }

  // fork: v-chain on s1, qk-chain on the default stream
  cudaEventRecord(evRoot, 0);
  cudaStreamWaitEvent(s1, evRoot, 0);
  gemm_v<<<dim3(NHW/128,4,NB),256,0,s1>>>(x,Wv);
  cudaEventRecord(evV, s1);

  gemm_qk<<<dim3(NHW/128,NB),256>>>(x,Wq,bq,Wk,bk);
  transpose_qk<<<dim3(NB*NIC,2),256>>>();
  logits_kernel<<<dim3(NB*96,2),256>>>();
  softmax_kernel<<<NB*NHW/8,256>>>();

  // join: agg needs v2 (s1) and A (default stream)
  cudaStreamWaitEvent(0, evV, 0);
  agg_v<<<dim3(2,NB*96,2),256>>>();
  combine_kernel<<<dim3(8,96,NB),256>>>(bv,gamma,x,out);
}